// round 6
// baseline (speedup 1.0000x reference)
#include <cuda_runtime.h>
#include <math.h>
#include <stdint.h>

#define HEADS  16
#define D_HEAD 64
#define DMODEL 1024
#define BATCH  4
#define SEQ    2048
#define MTOK   (BATCH * SEQ)   // 8192

// ---------------- device scratch (no runtime allocation) -------------------
__device__ float g_Q [(size_t)MTOK * DMODEL];   // rounded proj outputs
__device__ float g_K [(size_t)MTOK * DMODEL];
__device__ float g_V [(size_t)MTOK * DMODEL];
__device__ float g_A [(size_t)MTOK * DMODEL];   // rounded attention output
__device__ float g_rq[(size_t)MTOK * DMODEL];   // rounded inputs
__device__ float g_rk[(size_t)MTOK * DMODEL];
__device__ float g_rv[(size_t)MTOK * DMODEL];
__device__ float g_rWq[(size_t)DMODEL * DMODEL];
__device__ float g_rWk[(size_t)DMODEL * DMODEL];
__device__ float g_rWv[(size_t)DMODEL * DMODEL];
__device__ float g_rWo[(size_t)DMODEL * DMODEL];

// ---------------- helpers --------------------------------------------------
__device__ __forceinline__ uint32_t smem_u32(const void* p) {
    return (uint32_t)__cvta_generic_to_shared(p);
}
__device__ __forceinline__ void cpa16(uint32_t dst, const void* src) {
    asm volatile("cp.async.cg.shared.global [%0], [%1], 16;\n" :: "r"(dst), "l"(src));
}
__device__ __forceinline__ void cp_commit() {
    asm volatile("cp.async.commit_group;\n");
}
template <int N>
__device__ __forceinline__ void cp_wait() {
    asm volatile("cp.async.wait_group %0;\n" :: "n"(N));
}
// tf32 destination is an untyped b32 -> must use "=r" constraint
__device__ __forceinline__ float to_tf32(float x) {
    uint32_t r;
    asm("cvt.rna.tf32.f32 %0, %1;" : "=r"(r) : "f"(x));
    return __uint_as_float(r);
}
__device__ __forceinline__ void mma_tf32(float c[4], const uint32_t a[4], const uint32_t b[2]) {
    asm volatile(
        "mma.sync.aligned.m16n8k8.row.col.f32.tf32.tf32.f32 "
        "{%0,%1,%2,%3}, {%4,%5,%6,%7}, {%8,%9}, {%0,%1,%2,%3};"
        : "+f"(c[0]), "+f"(c[1]), "+f"(c[2]), "+f"(c[3])
        : "r"(a[0]), "r"(a[1]), "r"(a[2]), "r"(a[3]), "r"(b[0]), "r"(b[1]));
}

// ---------------- prep: round fp32 -> tf32 copies --------------------------
__global__ void round_kernel(const float4* __restrict__ in, float4* __restrict__ out, int n4) {
    int i = blockIdx.x * blockDim.x + threadIdx.x;
    if (i < n4) {
        float4 v = in[i];
        v.x = to_tf32(v.x); v.y = to_tf32(v.y);
        v.z = to_tf32(v.z); v.w = to_tf32(v.w);
        out[i] = v;
    }
}

// ---------------- tf32 GEMM: C[M,N] = A[M,K] @ W[K,N] + bias ---------------
// BM=128, BN=128, BK=32, 256 threads, 3-stage cp.async pipeline.
// As stored [m][k] ld=36 (frag banks 4r+c bijective), Bs [k][n] ld=136 (8k+n).
#define GLDA 36
#define GLDB 136
#define G_ASZ (128 * GLDA)          // 4608 floats
#define G_BSZ (32 * GLDB)           // 4352 floats
#define G_STG (G_ASZ + G_BSZ)       // 8960 floats = 35840 B/stage

__global__ __launch_bounds__(256, 2) void gemm_tf32_kernel(
    const float* __restrict__ A, const float* __restrict__ W,
    const float* __restrict__ bias, float* __restrict__ C, int round_out)
{
    extern __shared__ float sm[];
    const int tid = threadIdx.x, lane = tid & 31, wid = tid >> 5;
    const int m0 = blockIdx.y * 128, n0 = blockIdx.x * 128;
    const int wm = (wid >> 2) * 64, wn = (wid & 3) * 32;
    const int r = lane >> 2, cq = lane & 3;
    const int K = DMODEL, N = DMODEL;

    auto issue = [&](int s, int k0) {
        float* As = sm + s * G_STG;
        float* Bs = As + G_ASZ;
        #pragma unroll
        for (int i = 0; i < 4; i++) {                 // A: 128x32
            int ch = tid + 256 * i;
            int m = ch >> 3, kq = (ch & 7) * 4;
            cpa16(smem_u32(&As[m * GLDA + kq]),
                  A + (size_t)(m0 + m) * K + k0 + kq);
        }
        #pragma unroll
        for (int i = 0; i < 4; i++) {                 // B: 32x128
            int k = (tid >> 5) + 8 * i, n4 = (tid & 31) * 4;
            cpa16(smem_u32(&Bs[k * GLDB + n4]),
                  W + (size_t)(k0 + k) * N + n0 + n4);
        }
    };

    float acc[4][4][4];
    #pragma unroll
    for (int mi = 0; mi < 4; mi++)
        #pragma unroll
        for (int ni = 0; ni < 4; ni++)
            #pragma unroll
            for (int j = 0; j < 4; j++) acc[mi][ni][j] = 0.f;

    issue(0, 0);  cp_commit();
    issue(1, 32); cp_commit();

    const int NKT = K / 32;  // 32
    int st = 0;
    for (int kt = 0; kt < NKT; kt++) {
        cp_wait<1>();
        __syncthreads();
        const float* As = sm + st * G_STG;
        const float* Bs = As + G_ASZ;

        #pragma unroll
        for (int ks = 0; ks < 4; ks++) {
            const int kk = ks * 8;
            uint32_t af[4][4], bf[4][2];
            #pragma unroll
            for (int mi = 0; mi < 4; mi++) {
                const float* p = &As[(wm + 16 * mi + r) * GLDA + kk + cq];
                af[mi][0] = __float_as_uint(p[0]);
                af[mi][1] = __float_as_uint(p[8 * GLDA]);
                af[mi][2] = __float_as_uint(p[4]);
                af[mi][3] = __float_as_uint(p[8 * GLDA + 4]);
            }
            #pragma unroll
            for (int ni = 0; ni < 4; ni++) {
                const float* p = &Bs[(kk + cq) * GLDB + wn + 8 * ni + r];
                bf[ni][0] = __float_as_uint(p[0]);
                bf[ni][1] = __float_as_uint(p[4 * GLDB]);
            }
            #pragma unroll
            for (int mi = 0; mi < 4; mi++)
                #pragma unroll
                for (int ni = 0; ni < 4; ni++)
                    mma_tf32(acc[mi][ni], af[mi], bf[ni]);
        }

        int kn = kt + 2;
        if (kn < NKT) issue(kn % 3, kn * 32);
        cp_commit();
        st = (st + 1) % 3;
    }

    // epilogue
    #pragma unroll
    for (int mi = 0; mi < 4; mi++) {
        #pragma unroll
        for (int ni = 0; ni < 4; ni++) {
            int row = m0 + wm + 16 * mi + r;
            int col = n0 + wn + 8 * ni + 2 * cq;
            float2 bv = *(const float2*)&bias[col];
            float o0 = acc[mi][ni][0] + bv.x;
            float o1 = acc[mi][ni][1] + bv.y;
            float o2 = acc[mi][ni][2] + bv.x;
            float o3 = acc[mi][ni][3] + bv.y;
            if (round_out) {
                o0 = to_tf32(o0); o1 = to_tf32(o1);
                o2 = to_tf32(o2); o3 = to_tf32(o3);
            }
            float2 v0 = make_float2(o0, o1), v1 = make_float2(o2, o3);
            *(float2*)&C[(size_t)row * N + col] = v0;
            *(float2*)&C[(size_t)(row + 8) * N + col] = v1;
        }
    }
}

// ---------------- tensor-core causal flash attention -----------------------
// BQ=128, BKV=64. 256 threads = 8 warps, warp w owns q rows 16w..16w+15.
// Q frags register-resident; K/V double-buffered cp.async; P via smem.
#define LQ 68            // Qs/Ps row stride (banks 4r+c bijective)
#define LK 68            // Ks[kv][d]
#define LV 72            // Vs[kv][d] (banks 8k+n bijective)
#define ATT_Q (128 * LQ)
#define ATT_P (128 * LQ)
#define ATT_K (64 * LK)
#define ATT_V (64 * LV)

__global__ __launch_bounds__(256, 1) void attn_tf32_kernel(
    const float* __restrict__ Q, const float* __restrict__ K,
    const float* __restrict__ V, float* __restrict__ O)
{
    extern __shared__ float sm[];
    float* Qs = sm;
    float* Ps = Qs + ATT_Q;
    float* Kbuf0 = Ps + ATT_P;
    float* Vbuf0 = Kbuf0 + ATT_K;
    float* Kbuf1 = Vbuf0 + ATT_V;
    float* Vbuf1 = Kbuf1 + ATT_K;

    const int tid = threadIdx.x, lane = tid & 31, w = tid >> 5;
    const int r = lane >> 2, cq = lane & 3;
    const int bh = blockIdx.y, b = bh >> 4, h = bh & 15;
    const int qi = (int)(gridDim.x - 1 - blockIdx.x);   // heavy first
    const int qbase = qi * 128;

    const size_t headoff = (size_t)b * SEQ * DMODEL + (size_t)h * D_HEAD;
    const float* Qg = Q + headoff;
    const float* Kg = K + headoff;
    const float* Vg = V + headoff;

    // issue Q tile (128 x 64)
    #pragma unroll
    for (int i = 0; i < 8; i++) {
        int ch = tid + 256 * i;
        int q = ch >> 4, dq = (ch & 15) * 4;
        cpa16(smem_u32(&Qs[q * LQ + dq]),
              Qg + (size_t)(qbase + q) * DMODEL + dq);
    }
    auto issueKV = [&](int jt) {
        float* Kd = (jt & 1) ? Kbuf1 : Kbuf0;
        float* Vd = (jt & 1) ? Vbuf1 : Vbuf0;
        int base = jt * 64;
        #pragma unroll
        for (int i = 0; i < 4; i++) {
            int ch = tid + 256 * i;
            int kv = ch >> 4, dq = (ch & 15) * 4;
            cpa16(smem_u32(&Kd[kv * LK + dq]),
                  Kg + (size_t)(base + kv) * DMODEL + dq);
            cpa16(smem_u32(&Vd[kv * LV + dq]),
                  Vg + (size_t)(base + kv) * DMODEL + dq);
        }
    };
    issueKV(0);
    cp_commit();

    float o[8][4];
    #pragma unroll
    for (int ni = 0; ni < 8; ni++)
        #pragma unroll
        for (int j = 0; j < 4; j++) o[ni][j] = 0.f;
    float mr0 = -INFINITY, mr1 = -INFINITY, l0 = 0.f, l1 = 0.f;
    uint32_t qa[8][4];

    const int nt = 2 * qi + 2;
    for (int jt = 0; jt < nt; jt++) {
        if (jt + 1 < nt) issueKV(jt + 1);
        cp_commit();
        cp_wait<1>();
        __syncthreads();

        const float* Kc = (jt & 1) ? Kbuf1 : Kbuf0;
        const float* Vc = (jt & 1) ? Vbuf1 : Vbuf0;

        if (jt == 0) {   // Q fragments, once
            #pragma unroll
            for (int kj = 0; kj < 8; kj++) {
                const float* p = &Qs[(16 * w + r) * LQ + 8 * kj + cq];
                qa[kj][0] = __float_as_uint(p[0]);
                qa[kj][1] = __float_as_uint(p[8 * LQ]);
                qa[kj][2] = __float_as_uint(p[4]);
                qa[kj][3] = __float_as_uint(p[8 * LQ + 4]);
            }
        }

        // S = Q K^T  (16 x 64 per warp)
        float s[8][4];
        #pragma unroll
        for (int ni = 0; ni < 8; ni++)
            #pragma unroll
            for (int j = 0; j < 4; j++) s[ni][j] = 0.f;

        #pragma unroll
        for (int kj = 0; kj < 8; kj++) {
            #pragma unroll
            for (int ni = 0; ni < 8; ni++) {
                uint32_t bf[2];
                const float* p = &Kc[(8 * ni + r) * LK + 8 * kj + cq];
                bf[0] = __float_as_uint(p[0]);
                bf[1] = __float_as_uint(p[4]);
                mma_tf32(s[ni], qa[kj], bf);
            }
        }

        // online softmax
        const int kvb = jt * 64;
        const float scale = 0.125f;   // 1/sqrt(64)
        float rmax0 = -INFINITY, rmax1 = -INFINITY;
        if (kvb + 63 > qbase + 16 * w) {   // diagonal tiles: mask
            const int row0 = qbase + 16 * w + r;
            const int row1 = row0 + 8;
            #pragma unroll
            for (int ni = 0; ni < 8; ni++) {
                int c0 = kvb + 8 * ni + 2 * cq;
                float v0 = (c0     > row0) ? -INFINITY : s[ni][0] * scale;
                float v1 = (c0 + 1 > row0) ? -INFINITY : s[ni][1] * scale;
                float v2 = (c0     > row1) ? -INFINITY : s[ni][2] * scale;
                float v3 = (c0 + 1 > row1) ? -INFINITY : s[ni][3] * scale;
                s[ni][0] = v0; s[ni][1] = v1; s[ni][2] = v2; s[ni][3] = v3;
                rmax0 = fmaxf(rmax0, fmaxf(v0, v1));
                rmax1 = fmaxf(rmax1, fmaxf(v2, v3));
            }
        } else {
            #pragma unroll
            for (int ni = 0; ni < 8; ni++) {
                float v0 = s[ni][0] * scale, v1 = s[ni][1] * scale;
                float v2 = s[ni][2] * scale, v3 = s[ni][3] * scale;
                s[ni][0] = v0; s[ni][1] = v1; s[ni][2] = v2; s[ni][3] = v3;
                rmax0 = fmaxf(rmax0, fmaxf(v0, v1));
                rmax1 = fmaxf(rmax1, fmaxf(v2, v3));
            }
        }
        #pragma unroll
        for (int off = 1; off < 4; off <<= 1) {
            rmax0 = fmaxf(rmax0, __shfl_xor_sync(0xffffffffu, rmax0, off));
            rmax1 = fmaxf(rmax1, __shfl_xor_sync(0xffffffffu, rmax1, off));
        }
        const float mn0 = fmaxf(mr0, rmax0);
        const float mn1 = fmaxf(mr1, rmax1);
        const float al0 = __expf(mr0 - mn0);
        const float al1 = __expf(mr1 - mn1);
        mr0 = mn0; mr1 = mn1;

        float rs0 = 0.f, rs1 = 0.f;
        #pragma unroll
        for (int ni = 0; ni < 8; ni++) {
            float p0 = __expf(s[ni][0] - mn0);
            float p1 = __expf(s[ni][1] - mn0);
            float p2 = __expf(s[ni][2] - mn1);
            float p3 = __expf(s[ni][3] - mn1);
            rs0 += p0 + p1;
            rs1 += p2 + p3;
            float2 w0 = make_float2(to_tf32(p0), to_tf32(p1));
            float2 w1 = make_float2(to_tf32(p2), to_tf32(p3));
            *(float2*)&Ps[(16 * w + r) * LQ + 8 * ni + 2 * cq] = w0;
            *(float2*)&Ps[(16 * w + r + 8) * LQ + 8 * ni + 2 * cq] = w1;
        }
        #pragma unroll
        for (int off = 1; off < 4; off <<= 1) {
            rs0 += __shfl_xor_sync(0xffffffffu, rs0, off);
            rs1 += __shfl_xor_sync(0xffffffffu, rs1, off);
        }
        l0 = l0 * al0 + rs0;
        l1 = l1 * al1 + rs1;
        #pragma unroll
        for (int ni = 0; ni < 8; ni++) {
            o[ni][0] *= al0; o[ni][1] *= al0;
            o[ni][2] *= al1; o[ni][3] *= al1;
        }
        __syncwarp();

        // O += P V
        #pragma unroll
        for (int kj = 0; kj < 8; kj++) {
            uint32_t pa[4];
            const float* pp = &Ps[(16 * w + r) * LQ + 8 * kj + cq];
            pa[0] = __float_as_uint(pp[0]);
            pa[1] = __float_as_uint(pp[8 * LQ]);
            pa[2] = __float_as_uint(pp[4]);
            pa[3] = __float_as_uint(pp[8 * LQ + 4]);
            #pragma unroll
            for (int ni = 0; ni < 8; ni++) {
                uint32_t bf[2];
                const float* vp = &Vc[(8 * kj + cq) * LV + 8 * ni + r];
                bf[0] = __float_as_uint(vp[0]);
                bf[1] = __float_as_uint(vp[4 * LV]);
                mma_tf32(o[ni], pa, bf);
            }
        }
        __syncthreads();
    }

    // epilogue: normalize, round to tf32 (feeds final GEMM), store
    const float inv0 = 1.f / l0, inv1 = 1.f / l1;
    const int row0 = qbase + 16 * w + r;
    #pragma unroll
    for (int ni = 0; ni < 8; ni++) {
        int col = 8 * ni + 2 * cq;
        float2 v0 = make_float2(to_tf32(o[ni][0] * inv0), to_tf32(o[ni][1] * inv0));
        float2 v1 = make_float2(to_tf32(o[ni][2] * inv1), to_tf32(o[ni][3] * inv1));
        *(float2*)&O[headoff + (size_t)row0 * DMODEL + col] = v0;
        *(float2*)&O[headoff + (size_t)(row0 + 8) * DMODEL + col] = v1;
    }
}

// ---------------------------------------------------------------------------
extern "C" void kernel_launch(void* const* d_in, const int* in_sizes, int n_in,
                              void* d_out, int out_size)
{
    const float* q  = (const float*)d_in[0];
    const float* k  = (const float*)d_in[1];
    const float* v  = (const float*)d_in[2];
    const float* Wq = (const float*)d_in[3];
    const float* bq = (const float*)d_in[4];
    const float* Wk = (const float*)d_in[5];
    const float* bk = (const float*)d_in[6];
    const float* Wv = (const float*)d_in[7];
    const float* bv = (const float*)d_in[8];
    const float* Wo = (const float*)d_in[9];
    const float* bo = (const float*)d_in[10];
    float* out = (float*)d_out;

    float *gQ, *gK, *gV, *gA, *rq, *rk, *rv, *rWq, *rWk, *rWv, *rWo;
    cudaGetSymbolAddress((void**)&gQ, g_Q);
    cudaGetSymbolAddress((void**)&gK, g_K);
    cudaGetSymbolAddress((void**)&gV, g_V);
    cudaGetSymbolAddress((void**)&gA, g_A);
    cudaGetSymbolAddress((void**)&rq, g_rq);
    cudaGetSymbolAddress((void**)&rk, g_rk);
    cudaGetSymbolAddress((void**)&rv, g_rv);
    cudaGetSymbolAddress((void**)&rWq, g_rWq);
    cudaGetSymbolAddress((void**)&rWk, g_rWk);
    cudaGetSymbolAddress((void**)&rWv, g_rWv);
    cudaGetSymbolAddress((void**)&rWo, g_rWo);

    // prep: tf32-round inputs and weights
    const int nin4 = MTOK * DMODEL / 4;     // 2097152
    const int nw4  = DMODEL * DMODEL / 4;   // 262144
    round_kernel<<<nin4 / 256, 256>>>((const float4*)q, (float4*)rq, nin4);
    round_kernel<<<nin4 / 256, 256>>>((const float4*)k, (float4*)rk, nin4);
    round_kernel<<<nin4 / 256, 256>>>((const float4*)v, (float4*)rv, nin4);
    round_kernel<<<nw4 / 256, 256>>>((const float4*)Wq, (float4*)rWq, nw4);
    round_kernel<<<nw4 / 256, 256>>>((const float4*)Wk, (float4*)rWk, nw4);
    round_kernel<<<nw4 / 256, 256>>>((const float4*)Wv, (float4*)rWv, nw4);
    round_kernel<<<nw4 / 256, 256>>>((const float4*)Wo, (float4*)rWo, nw4);

    const int gemm_smem = 3 * G_STG * (int)sizeof(float);   // 107520
    cudaFuncSetAttribute(gemm_tf32_kernel,
                         cudaFuncAttributeMaxDynamicSharedMemorySize, gemm_smem);
    const dim3 gblk(DMODEL / 128, MTOK / 128);   // (8, 64)
    gemm_tf32_kernel<<<gblk, 256, gemm_smem>>>(rq, rWq, bq, gQ, 1);
    gemm_tf32_kernel<<<gblk, 256, gemm_smem>>>(rk, rWk, bk, gK, 1);
    gemm_tf32_kernel<<<gblk, 256, gemm_smem>>>(rv, rWv, bv, gV, 1);

    const int attn_smem = (ATT_Q + ATT_P + 2 * (ATT_K + ATT_V)) * (int)sizeof(float); // 141312
    cudaFuncSetAttribute(attn_tf32_kernel,
                         cudaFuncAttributeMaxDynamicSharedMemorySize, attn_smem);
    const dim3 agrid(SEQ / 128, BATCH * HEADS);  // (16, 64)
    attn_tf32_kernel<<<agrid, 256, attn_smem>>>(gQ, gK, gV, gA);

    gemm_tf32_kernel<<<gblk, 256, gemm_smem>>>(gA, rWo, bo, out, 0);
}

// round 7
// speedup vs baseline: 1.0096x; 1.0096x over previous
#include <cuda_runtime.h>
#include <math.h>
#include <stdint.h>

#define HEADS  16
#define D_HEAD 64
#define DMODEL 1024
#define BATCH  4
#define SEQ    2048
#define MTOK   (BATCH * SEQ)   // 8192

// ---------------- device scratch (no runtime allocation) -------------------
__device__ float g_Q[(size_t)MTOK * DMODEL];
__device__ float g_K[(size_t)MTOK * DMODEL];
__device__ float g_V[(size_t)MTOK * DMODEL];
__device__ float g_A[(size_t)MTOK * DMODEL];

// ---------------- helpers --------------------------------------------------
__device__ __forceinline__ uint32_t smem_u32(const void* p) {
    return (uint32_t)__cvta_generic_to_shared(p);
}
__device__ __forceinline__ void cpa16(uint32_t dst, const void* src) {
    asm volatile("cp.async.cg.shared.global [%0], [%1], 16;\n" :: "r"(dst), "l"(src));
}
__device__ __forceinline__ void cp_commit() {
    asm volatile("cp.async.commit_group;\n");
}
template <int N>
__device__ __forceinline__ void cp_wait() {
    asm volatile("cp.async.wait_group %0;\n" :: "n"(N));
}
// tf32 destination is an untyped b32 -> "=r" constraint
__device__ __forceinline__ float to_tf32(float x) {
    uint32_t r;
    asm("cvt.rna.tf32.f32 %0, %1;" : "=r"(r) : "f"(x));
    return __uint_as_float(r);
}
__device__ __forceinline__ uint32_t tf32_u(float x) {
    uint32_t r;
    asm("cvt.rna.tf32.f32 %0, %1;" : "=r"(r) : "f"(x));
    return r;
}
__device__ __forceinline__ void mma_tf32(float c[4], const uint32_t a[4], const uint32_t b[2]) {
    asm volatile(
        "mma.sync.aligned.m16n8k8.row.col.f32.tf32.tf32.f32 "
        "{%0,%1,%2,%3}, {%4,%5,%6,%7}, {%8,%9}, {%0,%1,%2,%3};"
        : "+f"(c[0]), "+f"(c[1]), "+f"(c[2]), "+f"(c[3])
        : "r"(a[0]), "r"(a[1]), "r"(a[2]), "r"(a[3]), "r"(b[0]), "r"(b[1]));
}

// ---------------- tf32 GEMM: C[M,N] = A[M,K] @ W[K,N] + bias ---------------
// BM=128, BN=128, BK=32, 256 threads, 3-stage cp.async pipeline.
// Raw fp32 operands; cvt.rna applied to fragments in-register (ALU pipe idle).
// Batched over blockIdx.z: selects (A, W, bias, C) triple.
#define GLDA 36
#define GLDB 136
#define G_ASZ (128 * GLDA)          // 4608 floats
#define G_BSZ (32 * GLDB)           // 4352 floats
#define G_STG (G_ASZ + G_BSZ)       // 8960 floats = 35840 B/stage

__global__ __launch_bounds__(256, 2) void gemm_tf32_kernel(
    const float* __restrict__ A0, const float* __restrict__ A1, const float* __restrict__ A2,
    const float* __restrict__ W0, const float* __restrict__ W1, const float* __restrict__ W2,
    const float* __restrict__ b0, const float* __restrict__ b1, const float* __restrict__ b2,
    float* __restrict__ C0, float* __restrict__ C1, float* __restrict__ C2,
    int round_out)
{
    extern __shared__ float sm[];
    const int bz = blockIdx.z;
    const float* A    = (bz == 0) ? A0 : (bz == 1) ? A1 : A2;
    const float* W    = (bz == 0) ? W0 : (bz == 1) ? W1 : W2;
    const float* bias = (bz == 0) ? b0 : (bz == 1) ? b1 : b2;
    float*       C    = (bz == 0) ? C0 : (bz == 1) ? C1 : C2;

    const int tid = threadIdx.x, lane = tid & 31, wid = tid >> 5;
    const int m0 = blockIdx.y * 128, n0 = blockIdx.x * 128;
    const int wm = (wid >> 2) * 64, wn = (wid & 3) * 32;
    const int r = lane >> 2, cq = lane & 3;
    const int K = DMODEL, N = DMODEL;

    auto issue = [&](int s, int k0) {
        float* As = sm + s * G_STG;
        float* Bs = As + G_ASZ;
        #pragma unroll
        for (int i = 0; i < 4; i++) {                 // A: 128x32
            int ch = tid + 256 * i;
            int m = ch >> 3, kq = (ch & 7) * 4;
            cpa16(smem_u32(&As[m * GLDA + kq]),
                  A + (size_t)(m0 + m) * K + k0 + kq);
        }
        #pragma unroll
        for (int i = 0; i < 4; i++) {                 // B: 32x128
            int k = (tid >> 5) + 8 * i, n4 = (tid & 31) * 4;
            cpa16(smem_u32(&Bs[k * GLDB + n4]),
                  W + (size_t)(k0 + k) * N + n0 + n4);
        }
    };

    float acc[4][4][4];
    #pragma unroll
    for (int mi = 0; mi < 4; mi++)
        #pragma unroll
        for (int ni = 0; ni < 4; ni++)
            #pragma unroll
            for (int j = 0; j < 4; j++) acc[mi][ni][j] = 0.f;

    issue(0, 0);  cp_commit();
    issue(1, 32); cp_commit();

    const int NKT = K / 32;  // 32
    int st = 0;
    for (int kt = 0; kt < NKT; kt++) {
        cp_wait<1>();
        __syncthreads();
        const float* As = sm + st * G_STG;
        const float* Bs = As + G_ASZ;

        #pragma unroll
        for (int ks = 0; ks < 4; ks++) {
            const int kk = ks * 8;
            uint32_t af[4][4], bf[4][2];
            #pragma unroll
            for (int mi = 0; mi < 4; mi++) {
                const float* p = &As[(wm + 16 * mi + r) * GLDA + kk + cq];
                af[mi][0] = tf32_u(p[0]);
                af[mi][1] = tf32_u(p[8 * GLDA]);
                af[mi][2] = tf32_u(p[4]);
                af[mi][3] = tf32_u(p[8 * GLDA + 4]);
            }
            #pragma unroll
            for (int ni = 0; ni < 4; ni++) {
                const float* p = &Bs[(kk + cq) * GLDB + wn + 8 * ni + r];
                bf[ni][0] = tf32_u(p[0]);
                bf[ni][1] = tf32_u(p[4 * GLDB]);
            }
            #pragma unroll
            for (int mi = 0; mi < 4; mi++)
                #pragma unroll
                for (int ni = 0; ni < 4; ni++)
                    mma_tf32(acc[mi][ni], af[mi], bf[ni]);
        }

        int kn = kt + 2;
        if (kn < NKT) issue(kn % 3, kn * 32);
        cp_commit();
        st = (st + 1) % 3;
    }

    // epilogue
    #pragma unroll
    for (int mi = 0; mi < 4; mi++) {
        #pragma unroll
        for (int ni = 0; ni < 4; ni++) {
            int row = m0 + wm + 16 * mi + r;
            int col = n0 + wn + 8 * ni + 2 * cq;
            float2 bv = *(const float2*)&bias[col];
            float o0 = acc[mi][ni][0] + bv.x;
            float o1 = acc[mi][ni][1] + bv.y;
            float o2 = acc[mi][ni][2] + bv.x;
            float o3 = acc[mi][ni][3] + bv.y;
            if (round_out) {
                o0 = to_tf32(o0); o1 = to_tf32(o1);
                o2 = to_tf32(o2); o3 = to_tf32(o3);
            }
            float2 v0 = make_float2(o0, o1), v1 = make_float2(o2, o3);
            *(float2*)&C[(size_t)row * N + col] = v0;
            *(float2*)&C[(size_t)(row + 8) * N + col] = v1;
        }
    }
}

// ---------------- tensor-core causal flash attention -----------------------
// BQ=128, BKV=64. 256 threads = 8 warps, warp w owns q rows 16w..16w+15.
// Q staged through KV buffers then register-resident; K/V double-buffered;
// P repacked C-frag -> A-frag via shuffles (no smem round-trip).
// smem = 2*(K+V) tiles = 70 KB -> 2 CTAs/SM.
#define LK 68            // Ks[kv][d]
#define LV 72            // Vs[kv][d]
#define ATT_K (64 * LK)
#define ATT_V (64 * LV)

__global__ __launch_bounds__(256, 2) void attn_tf32_kernel(
    const float* __restrict__ Q, const float* __restrict__ K,
    const float* __restrict__ V, float* __restrict__ O)
{
    extern __shared__ float sm[];
    float* Kbuf0 = sm;
    float* Vbuf0 = Kbuf0 + ATT_K;
    float* Kbuf1 = Vbuf0 + ATT_V;
    float* Vbuf1 = Kbuf1 + ATT_K;

    const int tid = threadIdx.x, lane = tid & 31, w = tid >> 5;
    const int r = lane >> 2, cq = lane & 3;
    const int bh = blockIdx.y, b = bh >> 4, h = bh & 15;
    const int qi = (int)(gridDim.x - 1 - blockIdx.x);   // heavy first
    const int qbase = qi * 128;

    const size_t headoff = (size_t)b * SEQ * DMODEL + (size_t)h * D_HEAD;
    const float* Qg = Q + headoff;
    const float* Kg = K + headoff;
    const float* Vg = V + headoff;

    // ---- stage Q tile (128x64) through Kbuf0 (rows 0..63) / Vbuf0 (64..127)
    #pragma unroll
    for (int i = 0; i < 8; i++) {
        int ch = tid + 256 * i;
        int q = ch >> 4, dq = (ch & 15) * 4;
        float* dst = (q < 64) ? &Kbuf0[q * LK + dq] : &Vbuf0[(q - 64) * LV + dq];
        cpa16(smem_u32(dst), Qg + (size_t)(qbase + q) * DMODEL + dq);
    }
    cp_commit();
    cp_wait<0>();
    __syncthreads();

    // extract Q fragments (Q is pre-rounded tf32 from the projection GEMM)
    uint32_t qa[8][4];
    {
        const int qrow = 16 * w + r;
        const float* qb = (w < 4) ? &Kbuf0[qrow * LK] : &Vbuf0[(qrow - 64) * LV];
        const int ldq = (w < 4) ? LK : LV;
        #pragma unroll
        for (int kj = 0; kj < 8; kj++) {
            const float* p = qb + 8 * kj + cq;
            qa[kj][0] = __float_as_uint(p[0]);
            qa[kj][1] = __float_as_uint(p[8 * ldq]);
            qa[kj][2] = __float_as_uint(p[4]);
            qa[kj][3] = __float_as_uint(p[8 * ldq + 4]);
        }
    }
    __syncthreads();   // all fragments extracted before buffers are reused

    auto issueKV = [&](int jt) {
        float* Kd = (jt & 1) ? Kbuf1 : Kbuf0;
        float* Vd = (jt & 1) ? Vbuf1 : Vbuf0;
        int base = jt * 64;
        #pragma unroll
        for (int i = 0; i < 4; i++) {
            int ch = tid + 256 * i;
            int kv = ch >> 4, dq = (ch & 15) * 4;
            cpa16(smem_u32(&Kd[kv * LK + dq]),
                  Kg + (size_t)(base + kv) * DMODEL + dq);
            cpa16(smem_u32(&Vd[kv * LV + dq]),
                  Vg + (size_t)(base + kv) * DMODEL + dq);
        }
    };
    issueKV(0);
    cp_commit();

    float o[8][4];
    #pragma unroll
    for (int ni = 0; ni < 8; ni++)
        #pragma unroll
        for (int j = 0; j < 4; j++) o[ni][j] = 0.f;
    float mr0 = -INFINITY, mr1 = -INFINITY, l0 = 0.f, l1 = 0.f;

    const int nt = 2 * qi + 2;
    for (int jt = 0; jt < nt; jt++) {
        if (jt + 1 < nt) issueKV(jt + 1);
        cp_commit();
        cp_wait<1>();
        __syncthreads();

        const float* Kc = (jt & 1) ? Kbuf1 : Kbuf0;
        const float* Vc = (jt & 1) ? Vbuf1 : Vbuf0;

        // S = Q K^T  (16 x 64 per warp)
        float s[8][4];
        #pragma unroll
        for (int ni = 0; ni < 8; ni++)
            #pragma unroll
            for (int j = 0; j < 4; j++) s[ni][j] = 0.f;

        #pragma unroll
        for (int kj = 0; kj < 8; kj++) {
            #pragma unroll
            for (int ni = 0; ni < 8; ni++) {
                uint32_t bf[2];
                const float* p = &Kc[(8 * ni + r) * LK + 8 * kj + cq];
                bf[0] = __float_as_uint(p[0]);
                bf[1] = __float_as_uint(p[4]);
                mma_tf32(s[ni], qa[kj], bf);
            }
        }

        // online softmax
        const int kvb = jt * 64;
        const float scale = 0.125f;   // 1/sqrt(64)
        float rmax0 = -INFINITY, rmax1 = -INFINITY;
        if (kvb + 63 > qbase + 16 * w) {   // diagonal tiles: mask
            const int row0 = qbase + 16 * w + r;
            const int row1 = row0 + 8;
            #pragma unroll
            for (int ni = 0; ni < 8; ni++) {
                int c0 = kvb + 8 * ni + 2 * cq;
                float v0 = (c0     > row0) ? -INFINITY : s[ni][0] * scale;
                float v1 = (c0 + 1 > row0) ? -INFINITY : s[ni][1] * scale;
                float v2 = (c0     > row1) ? -INFINITY : s[ni][2] * scale;
                float v3 = (c0 + 1 > row1) ? -INFINITY : s[ni][3] * scale;
                s[ni][0] = v0; s[ni][1] = v1; s[ni][2] = v2; s[ni][3] = v3;
                rmax0 = fmaxf(rmax0, fmaxf(v0, v1));
                rmax1 = fmaxf(rmax1, fmaxf(v2, v3));
            }
        } else {
            #pragma unroll
            for (int ni = 0; ni < 8; ni++) {
                float v0 = s[ni][0] * scale, v1 = s[ni][1] * scale;
                float v2 = s[ni][2] * scale, v3 = s[ni][3] * scale;
                s[ni][0] = v0; s[ni][1] = v1; s[ni][2] = v2; s[ni][3] = v3;
                rmax0 = fmaxf(rmax0, fmaxf(v0, v1));
                rmax1 = fmaxf(rmax1, fmaxf(v2, v3));
            }
        }
        #pragma unroll
        for (int off = 1; off < 4; off <<= 1) {
            rmax0 = fmaxf(rmax0, __shfl_xor_sync(0xffffffffu, rmax0, off));
            rmax1 = fmaxf(rmax1, __shfl_xor_sync(0xffffffffu, rmax1, off));
        }
        const float mn0 = fmaxf(mr0, rmax0);
        const float mn1 = fmaxf(mr1, rmax1);
        const float al0 = __expf(mr0 - mn0);
        const float al1 = __expf(mr1 - mn1);
        mr0 = mn0; mr1 = mn1;

        float rs0 = 0.f, rs1 = 0.f;
        #pragma unroll
        for (int ni = 0; ni < 8; ni++) {
            s[ni][0] = __expf(s[ni][0] - mn0);
            s[ni][1] = __expf(s[ni][1] - mn0);
            s[ni][2] = __expf(s[ni][2] - mn1);
            s[ni][3] = __expf(s[ni][3] - mn1);
            rs0 += s[ni][0] + s[ni][1];
            rs1 += s[ni][2] + s[ni][3];
        }
        #pragma unroll
        for (int off = 1; off < 4; off <<= 1) {
            rs0 += __shfl_xor_sync(0xffffffffu, rs0, off);
            rs1 += __shfl_xor_sync(0xffffffffu, rs1, off);
        }
        l0 = l0 * al0 + rs0;
        l1 = l1 * al1 + rs1;
        #pragma unroll
        for (int ni = 0; ni < 8; ni++) {
            o[ni][0] *= al0; o[ni][1] *= al0;
            o[ni][2] *= al1; o[ni][3] *= al1;
        }

        // repack P: C-fragment (s) -> A-fragment (pa) via shuffles, tf32-rounded.
        // target a0 = P(r, 8k+cq) lives at lane 4r+(cq>>1), element cq&1;
        //        a2 = P(r, 8k+cq+4) at lane 4r+2+(cq>>1), element cq&1;
        //        a1/a3 same lanes, elements 2+(cq&1).
        uint32_t pa[8][4];
        const int srcA = 4 * r + (cq >> 1);
        const int srcB = srcA + 2;
        const bool oddc = (cq & 1);
        #pragma unroll
        for (int ni = 0; ni < 8; ni++) {
            float p0 = to_tf32(s[ni][0]);
            float p1 = to_tf32(s[ni][1]);
            float p2 = to_tf32(s[ni][2]);
            float p3 = to_tf32(s[ni][3]);
            float a0a = __shfl_sync(0xffffffffu, p0, srcA);
            float a0b = __shfl_sync(0xffffffffu, p1, srcA);
            float a1a = __shfl_sync(0xffffffffu, p2, srcA);
            float a1b = __shfl_sync(0xffffffffu, p3, srcA);
            float a2a = __shfl_sync(0xffffffffu, p0, srcB);
            float a2b = __shfl_sync(0xffffffffu, p1, srcB);
            float a3a = __shfl_sync(0xffffffffu, p2, srcB);
            float a3b = __shfl_sync(0xffffffffu, p3, srcB);
            pa[ni][0] = __float_as_uint(oddc ? a0b : a0a);
            pa[ni][1] = __float_as_uint(oddc ? a1b : a1a);
            pa[ni][2] = __float_as_uint(oddc ? a2b : a2a);
            pa[ni][3] = __float_as_uint(oddc ? a3b : a3a);
        }

        // O += P V
        #pragma unroll
        for (int kj = 0; kj < 8; kj++) {
            #pragma unroll
            for (int ni = 0; ni < 8; ni++) {
                uint32_t bf[2];
                const float* vp = &Vc[(8 * kj + cq) * LV + 8 * ni + r];
                bf[0] = __float_as_uint(vp[0]);
                bf[1] = __float_as_uint(vp[4 * LV]);
                mma_tf32(o[ni], pa[kj], bf);
            }
        }
        __syncthreads();   // protect K/V buffer reuse by next-next issue
    }

    // epilogue: normalize and store (final GEMM does its own tf32 rounding)
    const float inv0 = 1.f / l0, inv1 = 1.f / l1;
    const int row0 = qbase + 16 * w + r;
    #pragma unroll
    for (int ni = 0; ni < 8; ni++) {
        int col = 8 * ni + 2 * cq;
        float2 v0 = make_float2(o[ni][0] * inv0, o[ni][1] * inv0);
        float2 v1 = make_float2(o[ni][2] * inv1, o[ni][3] * inv1);
        *(float2*)&O[headoff + (size_t)row0 * DMODEL + col] = v0;
        *(float2*)&O[headoff + (size_t)(row0 + 8) * DMODEL + col] = v1;
    }
}

// ---------------------------------------------------------------------------
extern "C" void kernel_launch(void* const* d_in, const int* in_sizes, int n_in,
                              void* d_out, int out_size)
{
    const float* q  = (const float*)d_in[0];
    const float* k  = (const float*)d_in[1];
    const float* v  = (const float*)d_in[2];
    const float* Wq = (const float*)d_in[3];
    const float* bq = (const float*)d_in[4];
    const float* Wk = (const float*)d_in[5];
    const float* bk = (const float*)d_in[6];
    const float* Wv = (const float*)d_in[7];
    const float* bv = (const float*)d_in[8];
    const float* Wo = (const float*)d_in[9];
    const float* bo = (const float*)d_in[10];
    float* out = (float*)d_out;

    float *gQ, *gK, *gV, *gA;
    cudaGetSymbolAddress((void**)&gQ, g_Q);
    cudaGetSymbolAddress((void**)&gK, g_K);
    cudaGetSymbolAddress((void**)&gV, g_V);
    cudaGetSymbolAddress((void**)&gA, g_A);

    const int gemm_smem = 3 * G_STG * (int)sizeof(float);   // 107520
    cudaFuncSetAttribute(gemm_tf32_kernel,
                         cudaFuncAttributeMaxDynamicSharedMemorySize, gemm_smem);

    // batched Q/K/V projections (rounded outputs feed attention)
    const dim3 gqkv(DMODEL / 128, MTOK / 128, 3);   // (8, 64, 3)
    gemm_tf32_kernel<<<gqkv, 256, gemm_smem>>>(
        q, k, v,  Wq, Wk, Wv,  bq, bk, bv,  gQ, gK, gV, 1);

    const int attn_smem = 2 * (ATT_K + ATT_V) * (int)sizeof(float);   // 71680
    cudaFuncSetAttribute(attn_tf32_kernel,
                         cudaFuncAttributeMaxDynamicSharedMemorySize, attn_smem);
    const dim3 agrid(SEQ / 128, BATCH * HEADS);  // (16, 64)
    attn_tf32_kernel<<<agrid, 256, attn_smem>>>(gQ, gK, gV, gA);

    // output projection (raw fp32 out)
    const dim3 gout(DMODEL / 128, MTOK / 128, 1);
    gemm_tf32_kernel<<<gout, 256, gemm_smem>>>(
        gA, gA, gA,  Wo, Wo, Wo,  bo, bo, bo,  out, out, out, 0);
}

// round 8
// speedup vs baseline: 1.0099x; 1.0003x over previous
#include <cuda_runtime.h>
#include <math.h>
#include <stdint.h>

#define HEADS  16
#define D_HEAD 64
#define DMODEL 1024
#define BATCH  4
#define SEQ    2048
#define MTOK   (BATCH * SEQ)   // 8192

// ---------------- device scratch (no runtime allocation) -------------------
__device__ float g_Q[(size_t)MTOK * DMODEL];
__device__ float g_K[(size_t)MTOK * DMODEL];
__device__ float g_V[(size_t)MTOK * DMODEL];
__device__ float g_A[(size_t)MTOK * DMODEL];

// ---------------- helpers --------------------------------------------------
__device__ __forceinline__ uint32_t smem_u32(const void* p) {
    return (uint32_t)__cvta_generic_to_shared(p);
}
__device__ __forceinline__ void cpa16(uint32_t dst, const void* src) {
    asm volatile("cp.async.cg.shared.global [%0], [%1], 16;\n" :: "r"(dst), "l"(src));
}
__device__ __forceinline__ void cp_commit() {
    asm volatile("cp.async.commit_group;\n");
}
template <int N>
__device__ __forceinline__ void cp_wait() {
    asm volatile("cp.async.wait_group %0;\n" :: "n"(N));
}
// tf32 destination is an untyped b32 -> "=r" constraint
__device__ __forceinline__ float to_tf32(float x) {
    uint32_t r;
    asm("cvt.rna.tf32.f32 %0, %1;" : "=r"(r) : "f"(x));
    return __uint_as_float(r);
}
__device__ __forceinline__ uint32_t tf32_u(float x) {
    uint32_t r;
    asm("cvt.rna.tf32.f32 %0, %1;" : "=r"(r) : "f"(x));
    return r;
}
__device__ __forceinline__ void mma_tf32(float c[4], const uint32_t a[4], const uint32_t b[2]) {
    asm volatile(
        "mma.sync.aligned.m16n8k8.row.col.f32.tf32.tf32.f32 "
        "{%0,%1,%2,%3}, {%4,%5,%6,%7}, {%8,%9}, {%0,%1,%2,%3};"
        : "+f"(c[0]), "+f"(c[1]), "+f"(c[2]), "+f"(c[3])
        : "r"(a[0]), "r"(a[1]), "r"(a[2]), "r"(a[3]), "r"(b[0]), "r"(b[1]));
}

// ---------------- tf32 GEMM: C[M,N] = A[M,K] @ W[K,N] + bias ---------------
// BM=128, BN=128, BK=32, 256 threads, 3-stage cp.async pipeline.
// Raw fp32 operands; cvt.rna applied to fragments in-register (ALU pipe idle).
// Batched over blockIdx.z: selects (A, W, bias, C) triple.
#define GLDA 36
#define GLDB 136
#define G_ASZ (128 * GLDA)          // 4608 floats
#define G_BSZ (32 * GLDB)           // 4352 floats
#define G_STG (G_ASZ + G_BSZ)       // 8960 floats = 35840 B/stage

__global__ __launch_bounds__(256, 2) void gemm_tf32_kernel(
    const float* __restrict__ A0, const float* __restrict__ A1, const float* __restrict__ A2,
    const float* __restrict__ W0, const float* __restrict__ W1, const float* __restrict__ W2,
    const float* __restrict__ b0, const float* __restrict__ b1, const float* __restrict__ b2,
    float* __restrict__ C0, float* __restrict__ C1, float* __restrict__ C2,
    int round_out)
{
    extern __shared__ float sm[];
    const int bz = blockIdx.z;
    const float* A    = (bz == 0) ? A0 : (bz == 1) ? A1 : A2;
    const float* W    = (bz == 0) ? W0 : (bz == 1) ? W1 : W2;
    const float* bias = (bz == 0) ? b0 : (bz == 1) ? b1 : b2;
    float*       C    = (bz == 0) ? C0 : (bz == 1) ? C1 : C2;

    const int tid = threadIdx.x, lane = tid & 31, wid = tid >> 5;
    const int m0 = blockIdx.y * 128, n0 = blockIdx.x * 128;
    const int wm = (wid >> 2) * 64, wn = (wid & 3) * 32;
    const int r = lane >> 2, cq = lane & 3;
    const int K = DMODEL, N = DMODEL;

    auto issue = [&](int s, int k0) {
        float* As = sm + s * G_STG;
        float* Bs = As + G_ASZ;
        #pragma unroll
        for (int i = 0; i < 4; i++) {                 // A: 128x32
            int ch = tid + 256 * i;
            int m = ch >> 3, kq = (ch & 7) * 4;
            cpa16(smem_u32(&As[m * GLDA + kq]),
                  A + (size_t)(m0 + m) * K + k0 + kq);
        }
        #pragma unroll
        for (int i = 0; i < 4; i++) {                 // B: 32x128
            int k = (tid >> 5) + 8 * i, n4 = (tid & 31) * 4;
            cpa16(smem_u32(&Bs[k * GLDB + n4]),
                  W + (size_t)(k0 + k) * N + n0 + n4);
        }
    };

    float acc[4][4][4];
    #pragma unroll
    for (int mi = 0; mi < 4; mi++)
        #pragma unroll
        for (int ni = 0; ni < 4; ni++)
            #pragma unroll
            for (int j = 0; j < 4; j++) acc[mi][ni][j] = 0.f;

    issue(0, 0);  cp_commit();
    issue(1, 32); cp_commit();

    const int NKT = K / 32;  // 32
    int st = 0;
    for (int kt = 0; kt < NKT; kt++) {
        cp_wait<1>();
        __syncthreads();
        const float* As = sm + st * G_STG;
        const float* Bs = As + G_ASZ;

        #pragma unroll
        for (int ks = 0; ks < 4; ks++) {
            const int kk = ks * 8;
            uint32_t af[4][4], bf[4][2];
            #pragma unroll
            for (int mi = 0; mi < 4; mi++) {
                const float* p = &As[(wm + 16 * mi + r) * GLDA + kk + cq];
                af[mi][0] = tf32_u(p[0]);
                af[mi][1] = tf32_u(p[8 * GLDA]);
                af[mi][2] = tf32_u(p[4]);
                af[mi][3] = tf32_u(p[8 * GLDA + 4]);
            }
            #pragma unroll
            for (int ni = 0; ni < 4; ni++) {
                const float* p = &Bs[(kk + cq) * GLDB + wn + 8 * ni + r];
                bf[ni][0] = tf32_u(p[0]);
                bf[ni][1] = tf32_u(p[4 * GLDB]);
            }
            #pragma unroll
            for (int mi = 0; mi < 4; mi++)
                #pragma unroll
                for (int ni = 0; ni < 4; ni++)
                    mma_tf32(acc[mi][ni], af[mi], bf[ni]);
        }

        int kn = kt + 2;
        if (kn < NKT) issue(kn % 3, kn * 32);
        cp_commit();
        st = (st + 1) % 3;
    }

    // epilogue
    #pragma unroll
    for (int mi = 0; mi < 4; mi++) {
        #pragma unroll
        for (int ni = 0; ni < 4; ni++) {
            int row = m0 + wm + 16 * mi + r;
            int col = n0 + wn + 8 * ni + 2 * cq;
            float2 bv = *(const float2*)&bias[col];
            float o0 = acc[mi][ni][0] + bv.x;
            float o1 = acc[mi][ni][1] + bv.y;
            float o2 = acc[mi][ni][2] + bv.x;
            float o3 = acc[mi][ni][3] + bv.y;
            if (round_out) {
                o0 = to_tf32(o0); o1 = to_tf32(o1);
                o2 = to_tf32(o2); o3 = to_tf32(o3);
            }
            float2 v0 = make_float2(o0, o1), v1 = make_float2(o2, o3);
            *(float2*)&C[(size_t)row * N + col] = v0;
            *(float2*)&C[(size_t)(row + 8) * N + col] = v1;
        }
    }
}

// ---------------- tensor-core causal flash attention -----------------------
// BQ=128, BKV=64. 256 threads = 8 warps, warp w owns q rows 16w..16w+15.
// Q staged through KV buffers then register-resident; K/V double-buffered;
// P repacked C-frag -> A-frag via shuffles (no smem round-trip).
// smem = 2*(K+V) tiles = 70 KB -> 2 CTAs/SM.
#define LK 68            // Ks[kv][d]
#define LV 72            // Vs[kv][d]
#define ATT_K (64 * LK)
#define ATT_V (64 * LV)

__global__ __launch_bounds__(256, 2) void attn_tf32_kernel(
    const float* __restrict__ Q, const float* __restrict__ K,
    const float* __restrict__ V, float* __restrict__ O)
{
    extern __shared__ float sm[];
    float* Kbuf0 = sm;
    float* Vbuf0 = Kbuf0 + ATT_K;
    float* Kbuf1 = Vbuf0 + ATT_V;
    float* Vbuf1 = Kbuf1 + ATT_K;

    const int tid = threadIdx.x, lane = tid & 31, w = tid >> 5;
    const int r = lane >> 2, cq = lane & 3;
    const int bh = blockIdx.y, b = bh >> 4, h = bh & 15;
    const int qi = (int)(gridDim.x - 1 - blockIdx.x);   // heavy first
    const int qbase = qi * 128;

    const size_t headoff = (size_t)b * SEQ * DMODEL + (size_t)h * D_HEAD;
    const float* Qg = Q + headoff;
    const float* Kg = K + headoff;
    const float* Vg = V + headoff;

    // ---- stage Q tile (128x64) through Kbuf0 (rows 0..63) / Vbuf0 (64..127)
    #pragma unroll
    for (int i = 0; i < 8; i++) {
        int ch = tid + 256 * i;
        int q = ch >> 4, dq = (ch & 15) * 4;
        float* dst = (q < 64) ? &Kbuf0[q * LK + dq] : &Vbuf0[(q - 64) * LV + dq];
        cpa16(smem_u32(dst), Qg + (size_t)(qbase + q) * DMODEL + dq);
    }
    cp_commit();
    cp_wait<0>();
    __syncthreads();

    // extract Q fragments (Q is pre-rounded tf32 from the projection GEMM)
    uint32_t qa[8][4];
    {
        const int qrow = 16 * w + r;
        const float* qb = (w < 4) ? &Kbuf0[qrow * LK] : &Vbuf0[(qrow - 64) * LV];
        const int ldq = (w < 4) ? LK : LV;
        #pragma unroll
        for (int kj = 0; kj < 8; kj++) {
            const float* p = qb + 8 * kj + cq;
            qa[kj][0] = __float_as_uint(p[0]);
            qa[kj][1] = __float_as_uint(p[8 * ldq]);
            qa[kj][2] = __float_as_uint(p[4]);
            qa[kj][3] = __float_as_uint(p[8 * ldq + 4]);
        }
    }
    __syncthreads();   // all fragments extracted before buffers are reused

    auto issueKV = [&](int jt) {
        float* Kd = (jt & 1) ? Kbuf1 : Kbuf0;
        float* Vd = (jt & 1) ? Vbuf1 : Vbuf0;
        int base = jt * 64;
        #pragma unroll
        for (int i = 0; i < 4; i++) {
            int ch = tid + 256 * i;
            int kv = ch >> 4, dq = (ch & 15) * 4;
            cpa16(smem_u32(&Kd[kv * LK + dq]),
                  Kg + (size_t)(base + kv) * DMODEL + dq);
            cpa16(smem_u32(&Vd[kv * LV + dq]),
                  Vg + (size_t)(base + kv) * DMODEL + dq);
        }
    };
    issueKV(0);
    cp_commit();

    float o[8][4];
    #pragma unroll
    for (int ni = 0; ni < 8; ni++)
        #pragma unroll
        for (int j = 0; j < 4; j++) o[ni][j] = 0.f;
    float mr0 = -INFINITY, mr1 = -INFINITY, l0 = 0.f, l1 = 0.f;

    const int nt = 2 * qi + 2;
    for (int jt = 0; jt < nt; jt++) {
        if (jt + 1 < nt) issueKV(jt + 1);
        cp_commit();
        cp_wait<1>();
        __syncthreads();

        const float* Kc = (jt & 1) ? Kbuf1 : Kbuf0;
        const float* Vc = (jt & 1) ? Vbuf1 : Vbuf0;

        // S = Q K^T  (16 x 64 per warp)
        float s[8][4];
        #pragma unroll
        for (int ni = 0; ni < 8; ni++)
            #pragma unroll
            for (int j = 0; j < 4; j++) s[ni][j] = 0.f;

        #pragma unroll
        for (int kj = 0; kj < 8; kj++) {
            #pragma unroll
            for (int ni = 0; ni < 8; ni++) {
                uint32_t bf[2];
                const float* p = &Kc[(8 * ni + r) * LK + 8 * kj + cq];
                bf[0] = __float_as_uint(p[0]);
                bf[1] = __float_as_uint(p[4]);
                mma_tf32(s[ni], qa[kj], bf);
            }
        }

        // online softmax
        const int kvb = jt * 64;
        const float scale = 0.125f;   // 1/sqrt(64)
        float rmax0 = -INFINITY, rmax1 = -INFINITY;
        if (kvb + 63 > qbase + 16 * w) {   // diagonal tiles: mask
            const int row0 = qbase + 16 * w + r;
            const int row1 = row0 + 8;
            #pragma unroll
            for (int ni = 0; ni < 8; ni++) {
                int c0 = kvb + 8 * ni + 2 * cq;
                float v0 = (c0     > row0) ? -INFINITY : s[ni][0] * scale;
                float v1 = (c0 + 1 > row0) ? -INFINITY : s[ni][1] * scale;
                float v2 = (c0     > row1) ? -INFINITY : s[ni][2] * scale;
                float v3 = (c0 + 1 > row1) ? -INFINITY : s[ni][3] * scale;
                s[ni][0] = v0; s[ni][1] = v1; s[ni][2] = v2; s[ni][3] = v3;
                rmax0 = fmaxf(rmax0, fmaxf(v0, v1));
                rmax1 = fmaxf(rmax1, fmaxf(v2, v3));
            }
        } else {
            #pragma unroll
            for (int ni = 0; ni < 8; ni++) {
                float v0 = s[ni][0] * scale, v1 = s[ni][1] * scale;
                float v2 = s[ni][2] * scale, v3 = s[ni][3] * scale;
                s[ni][0] = v0; s[ni][1] = v1; s[ni][2] = v2; s[ni][3] = v3;
                rmax0 = fmaxf(rmax0, fmaxf(v0, v1));
                rmax1 = fmaxf(rmax1, fmaxf(v2, v3));
            }
        }
        #pragma unroll
        for (int off = 1; off < 4; off <<= 1) {
            rmax0 = fmaxf(rmax0, __shfl_xor_sync(0xffffffffu, rmax0, off));
            rmax1 = fmaxf(rmax1, __shfl_xor_sync(0xffffffffu, rmax1, off));
        }
        const float mn0 = fmaxf(mr0, rmax0);
        const float mn1 = fmaxf(mr1, rmax1);
        const float al0 = __expf(mr0 - mn0);
        const float al1 = __expf(mr1 - mn1);
        mr0 = mn0; mr1 = mn1;

        float rs0 = 0.f, rs1 = 0.f;
        #pragma unroll
        for (int ni = 0; ni < 8; ni++) {
            s[ni][0] = __expf(s[ni][0] - mn0);
            s[ni][1] = __expf(s[ni][1] - mn0);
            s[ni][2] = __expf(s[ni][2] - mn1);
            s[ni][3] = __expf(s[ni][3] - mn1);
            rs0 += s[ni][0] + s[ni][1];
            rs1 += s[ni][2] + s[ni][3];
        }
        #pragma unroll
        for (int off = 1; off < 4; off <<= 1) {
            rs0 += __shfl_xor_sync(0xffffffffu, rs0, off);
            rs1 += __shfl_xor_sync(0xffffffffu, rs1, off);
        }
        l0 = l0 * al0 + rs0;
        l1 = l1 * al1 + rs1;
        #pragma unroll
        for (int ni = 0; ni < 8; ni++) {
            o[ni][0] *= al0; o[ni][1] *= al0;
            o[ni][2] *= al1; o[ni][3] *= al1;
        }

        // repack P: C-fragment (s) -> A-fragment (pa) via shuffles, tf32-rounded.
        // target a0 = P(r, 8k+cq) lives at lane 4r+(cq>>1), element cq&1;
        //        a2 = P(r, 8k+cq+4) at lane 4r+2+(cq>>1), element cq&1;
        //        a1/a3 same lanes, elements 2+(cq&1).
        uint32_t pa[8][4];
        const int srcA = 4 * r + (cq >> 1);
        const int srcB = srcA + 2;
        const bool oddc = (cq & 1);
        #pragma unroll
        for (int ni = 0; ni < 8; ni++) {
            float p0 = to_tf32(s[ni][0]);
            float p1 = to_tf32(s[ni][1]);
            float p2 = to_tf32(s[ni][2]);
            float p3 = to_tf32(s[ni][3]);
            float a0a = __shfl_sync(0xffffffffu, p0, srcA);
            float a0b = __shfl_sync(0xffffffffu, p1, srcA);
            float a1a = __shfl_sync(0xffffffffu, p2, srcA);
            float a1b = __shfl_sync(0xffffffffu, p3, srcA);
            float a2a = __shfl_sync(0xffffffffu, p0, srcB);
            float a2b = __shfl_sync(0xffffffffu, p1, srcB);
            float a3a = __shfl_sync(0xffffffffu, p2, srcB);
            float a3b = __shfl_sync(0xffffffffu, p3, srcB);
            pa[ni][0] = __float_as_uint(oddc ? a0b : a0a);
            pa[ni][1] = __float_as_uint(oddc ? a1b : a1a);
            pa[ni][2] = __float_as_uint(oddc ? a2b : a2a);
            pa[ni][3] = __float_as_uint(oddc ? a3b : a3a);
        }

        // O += P V
        #pragma unroll
        for (int kj = 0; kj < 8; kj++) {
            #pragma unroll
            for (int ni = 0; ni < 8; ni++) {
                uint32_t bf[2];
                const float* vp = &Vc[(8 * kj + cq) * LV + 8 * ni + r];
                bf[0] = __float_as_uint(vp[0]);
                bf[1] = __float_as_uint(vp[4 * LV]);
                mma_tf32(o[ni], pa[kj], bf);
            }
        }
        __syncthreads();   // protect K/V buffer reuse by next-next issue
    }

    // epilogue: normalize and store (final GEMM does its own tf32 rounding)
    const float inv0 = 1.f / l0, inv1 = 1.f / l1;
    const int row0 = qbase + 16 * w + r;
    #pragma unroll
    for (int ni = 0; ni < 8; ni++) {
        int col = 8 * ni + 2 * cq;
        float2 v0 = make_float2(o[ni][0] * inv0, o[ni][1] * inv0);
        float2 v1 = make_float2(o[ni][2] * inv1, o[ni][3] * inv1);
        *(float2*)&O[headoff + (size_t)row0 * DMODEL + col] = v0;
        *(float2*)&O[headoff + (size_t)(row0 + 8) * DMODEL + col] = v1;
    }
}

// ---------------------------------------------------------------------------
extern "C" void kernel_launch(void* const* d_in, const int* in_sizes, int n_in,
                              void* d_out, int out_size)
{
    const float* q  = (const float*)d_in[0];
    const float* k  = (const float*)d_in[1];
    const float* v  = (const float*)d_in[2];
    const float* Wq = (const float*)d_in[3];
    const float* bq = (const float*)d_in[4];
    const float* Wk = (const float*)d_in[5];
    const float* bk = (const float*)d_in[6];
    const float* Wv = (const float*)d_in[7];
    const float* bv = (const float*)d_in[8];
    const float* Wo = (const float*)d_in[9];
    const float* bo = (const float*)d_in[10];
    float* out = (float*)d_out;

    float *gQ, *gK, *gV, *gA;
    cudaGetSymbolAddress((void**)&gQ, g_Q);
    cudaGetSymbolAddress((void**)&gK, g_K);
    cudaGetSymbolAddress((void**)&gV, g_V);
    cudaGetSymbolAddress((void**)&gA, g_A);

    const int gemm_smem = 3 * G_STG * (int)sizeof(float);   // 107520
    cudaFuncSetAttribute(gemm_tf32_kernel,
                         cudaFuncAttributeMaxDynamicSharedMemorySize, gemm_smem);

    // batched Q/K/V projections (rounded outputs feed attention)
    const dim3 gqkv(DMODEL / 128, MTOK / 128, 3);   // (8, 64, 3)
    gemm_tf32_kernel<<<gqkv, 256, gemm_smem>>>(
        q, k, v,  Wq, Wk, Wv,  bq, bk, bv,  gQ, gK, gV, 1);

    const int attn_smem = 2 * (ATT_K + ATT_V) * (int)sizeof(float);   // 71680
    cudaFuncSetAttribute(attn_tf32_kernel,
                         cudaFuncAttributeMaxDynamicSharedMemorySize, attn_smem);
    const dim3 agrid(SEQ / 128, BATCH * HEADS);  // (16, 64)
    attn_tf32_kernel<<<agrid, 256, attn_smem>>>(gQ, gK, gV, gA);

    // output projection (raw fp32 out)
    const dim3 gout(DMODEL / 128, MTOK / 128, 1);
    gemm_tf32_kernel<<<gout, 256, gemm_smem>>>(
        gA, gA, gA,  Wo, Wo, Wo,  bo, bo, bo,  out, out, out, 0);
}

// round 9
// speedup vs baseline: 1.0139x; 1.0040x over previous
#include <cuda_runtime.h>
#include <math.h>
#include <stdint.h>

#define HEADS  16
#define D_HEAD 64
#define DMODEL 1024
#define BATCH  4
#define SEQ    2048
#define MTOK   (BATCH * SEQ)   // 8192

// ---------------- device scratch (no runtime allocation) -------------------
__device__ float g_Q[(size_t)MTOK * DMODEL];
__device__ float g_K[(size_t)MTOK * DMODEL];
__device__ float g_V[(size_t)MTOK * DMODEL];
__device__ float g_A[(size_t)MTOK * DMODEL];

// ---------------- helpers --------------------------------------------------
__device__ __forceinline__ uint32_t smem_u32(const void* p) {
    return (uint32_t)__cvta_generic_to_shared(p);
}
__device__ __forceinline__ void cpa16(uint32_t dst, const void* src) {
    asm volatile("cp.async.cg.shared.global [%0], [%1], 16;\n" :: "r"(dst), "l"(src));
}
__device__ __forceinline__ void cp_commit() {
    asm volatile("cp.async.commit_group;\n");
}
template <int N>
__device__ __forceinline__ void cp_wait() {
    asm volatile("cp.async.wait_group %0;\n" :: "n"(N));
}
// tf32 destination is an untyped b32 -> "=r" constraint
__device__ __forceinline__ float to_tf32(float x) {
    uint32_t r;
    asm("cvt.rna.tf32.f32 %0, %1;" : "=r"(r) : "f"(x));
    return __uint_as_float(r);
}
__device__ __forceinline__ uint32_t tf32_u(float x) {
    uint32_t r;
    asm("cvt.rna.tf32.f32 %0, %1;" : "=r"(r) : "f"(x));
    return r;
}
__device__ __forceinline__ void mma_tf32(float c[4], const uint32_t a[4], const uint32_t b[2]) {
    asm volatile(
        "mma.sync.aligned.m16n8k8.row.col.f32.tf32.tf32.f32 "
        "{%0,%1,%2,%3}, {%4,%5,%6,%7}, {%8,%9}, {%0,%1,%2,%3};"
        : "+f"(c[0]), "+f"(c[1]), "+f"(c[2]), "+f"(c[3])
        : "r"(a[0]), "r"(a[1]), "r"(a[2]), "r"(a[3]), "r"(b[0]), "r"(b[1]));
}

// ---------------- tf32 GEMM: C[M,N] = A[M,K] @ W[K,N] + bias ---------------
// BM=128, BN=128, BK=32, 256 threads, 3-stage cp.async pipeline.
// Raw fp32 operands; cvt.rna applied to fragments in-register (ALU pipe idle).
// Batched over blockIdx.z: selects (A, W, bias, C) triple.
#define GLDA 36
#define GLDB 136
#define G_ASZ (128 * GLDA)          // 4608 floats
#define G_BSZ (32 * GLDB)           // 4352 floats
#define G_STG (G_ASZ + G_BSZ)       // 8960 floats = 35840 B/stage

__global__ __launch_bounds__(256, 2) void gemm_tf32_kernel(
    const float* __restrict__ A0, const float* __restrict__ A1, const float* __restrict__ A2,
    const float* __restrict__ W0, const float* __restrict__ W1, const float* __restrict__ W2,
    const float* __restrict__ b0, const float* __restrict__ b1, const float* __restrict__ b2,
    float* __restrict__ C0, float* __restrict__ C1, float* __restrict__ C2,
    int round_out)
{
    extern __shared__ float sm[];
    const int bz = blockIdx.z;
    const float* A    = (bz == 0) ? A0 : (bz == 1) ? A1 : A2;
    const float* W    = (bz == 0) ? W0 : (bz == 1) ? W1 : W2;
    const float* bias = (bz == 0) ? b0 : (bz == 1) ? b1 : b2;
    float*       C    = (bz == 0) ? C0 : (bz == 1) ? C1 : C2;

    const int tid = threadIdx.x, lane = tid & 31, wid = tid >> 5;
    const int m0 = blockIdx.y * 128, n0 = blockIdx.x * 128;
    const int wm = (wid >> 2) * 64, wn = (wid & 3) * 32;
    const int r = lane >> 2, cq = lane & 3;
    const int K = DMODEL, N = DMODEL;

    auto issue = [&](int s, int k0) {
        float* As = sm + s * G_STG;
        float* Bs = As + G_ASZ;
        #pragma unroll
        for (int i = 0; i < 4; i++) {                 // A: 128x32
            int ch = tid + 256 * i;
            int m = ch >> 3, kq = (ch & 7) * 4;
            cpa16(smem_u32(&As[m * GLDA + kq]),
                  A + (size_t)(m0 + m) * K + k0 + kq);
        }
        #pragma unroll
        for (int i = 0; i < 4; i++) {                 // B: 32x128
            int k = (tid >> 5) + 8 * i, n4 = (tid & 31) * 4;
            cpa16(smem_u32(&Bs[k * GLDB + n4]),
                  W + (size_t)(k0 + k) * N + n0 + n4);
        }
    };

    float acc[4][4][4];
    #pragma unroll
    for (int mi = 0; mi < 4; mi++)
        #pragma unroll
        for (int ni = 0; ni < 4; ni++)
            #pragma unroll
            for (int j = 0; j < 4; j++) acc[mi][ni][j] = 0.f;

    issue(0, 0);  cp_commit();
    issue(1, 32); cp_commit();

    const int NKT = K / 32;  // 32
    int st = 0;
    for (int kt = 0; kt < NKT; kt++) {
        cp_wait<1>();
        __syncthreads();
        const float* As = sm + st * G_STG;
        const float* Bs = As + G_ASZ;

        #pragma unroll
        for (int ks = 0; ks < 4; ks++) {
            const int kk = ks * 8;
            uint32_t af[4][4], bf[4][2];
            #pragma unroll
            for (int mi = 0; mi < 4; mi++) {
                const float* p = &As[(wm + 16 * mi + r) * GLDA + kk + cq];
                af[mi][0] = tf32_u(p[0]);
                af[mi][1] = tf32_u(p[8 * GLDA]);
                af[mi][2] = tf32_u(p[4]);
                af[mi][3] = tf32_u(p[8 * GLDA + 4]);
            }
            #pragma unroll
            for (int ni = 0; ni < 4; ni++) {
                const float* p = &Bs[(kk + cq) * GLDB + wn + 8 * ni + r];
                bf[ni][0] = tf32_u(p[0]);
                bf[ni][1] = tf32_u(p[4 * GLDB]);
            }
            #pragma unroll
            for (int mi = 0; mi < 4; mi++)
                #pragma unroll
                for (int ni = 0; ni < 4; ni++)
                    mma_tf32(acc[mi][ni], af[mi], bf[ni]);
        }

        int kn = kt + 2;
        if (kn < NKT) issue(kn % 3, kn * 32);
        cp_commit();
        st = (st + 1) % 3;
    }

    // epilogue
    #pragma unroll
    for (int mi = 0; mi < 4; mi++) {
        #pragma unroll
        for (int ni = 0; ni < 4; ni++) {
            int row = m0 + wm + 16 * mi + r;
            int col = n0 + wn + 8 * ni + 2 * cq;
            float2 bv = *(const float2*)&bias[col];
            float o0 = acc[mi][ni][0] + bv.x;
            float o1 = acc[mi][ni][1] + bv.y;
            float o2 = acc[mi][ni][2] + bv.x;
            float o3 = acc[mi][ni][3] + bv.y;
            if (round_out) {
                o0 = to_tf32(o0); o1 = to_tf32(o1);
                o2 = to_tf32(o2); o3 = to_tf32(o3);
            }
            float2 v0 = make_float2(o0, o1), v1 = make_float2(o2, o3);
            *(float2*)&C[(size_t)row * N + col] = v0;
            *(float2*)&C[(size_t)(row + 8) * N + col] = v1;
        }
    }
}

// ---------------- tensor-core causal flash attention -----------------------
// BQ=128, BKV=64. 256 threads = 8 warps, warp w owns q rows 16w..16w+15.
// Q staged through KV buffers then register-resident; K/V double-buffered;
// P repacked C-frag -> A-frag via shuffles (no smem round-trip).
// smem = 2*(K+V) tiles = 70 KB -> 2 CTAs/SM.
#define LK 68            // Ks[kv][d]
#define LV 72            // Vs[kv][d]
#define ATT_K (64 * LK)
#define ATT_V (64 * LV)

__global__ __launch_bounds__(256, 2) void attn_tf32_kernel(
    const float* __restrict__ Q, const float* __restrict__ K,
    const float* __restrict__ V, float* __restrict__ O)
{
    extern __shared__ float sm[];
    float* Kbuf0 = sm;
    float* Vbuf0 = Kbuf0 + ATT_K;
    float* Kbuf1 = Vbuf0 + ATT_V;
    float* Vbuf1 = Kbuf1 + ATT_K;

    const int tid = threadIdx.x, lane = tid & 31, w = tid >> 5;
    const int r = lane >> 2, cq = lane & 3;
    const int bh = blockIdx.y, b = bh >> 4, h = bh & 15;
    const int qi = (int)(gridDim.x - 1 - blockIdx.x);   // heavy first
    const int qbase = qi * 128;

    const size_t headoff = (size_t)b * SEQ * DMODEL + (size_t)h * D_HEAD;
    const float* Qg = Q + headoff;
    const float* Kg = K + headoff;
    const float* Vg = V + headoff;

    // ---- stage Q tile (128x64) through Kbuf0 (rows 0..63) / Vbuf0 (64..127)
    #pragma unroll
    for (int i = 0; i < 8; i++) {
        int ch = tid + 256 * i;
        int q = ch >> 4, dq = (ch & 15) * 4;
        float* dst = (q < 64) ? &Kbuf0[q * LK + dq] : &Vbuf0[(q - 64) * LV + dq];
        cpa16(smem_u32(dst), Qg + (size_t)(qbase + q) * DMODEL + dq);
    }
    cp_commit();
    cp_wait<0>();
    __syncthreads();

    // extract Q fragments (Q is pre-rounded tf32 from the projection GEMM)
    uint32_t qa[8][4];
    {
        const int qrow = 16 * w + r;
        const float* qb = (w < 4) ? &Kbuf0[qrow * LK] : &Vbuf0[(qrow - 64) * LV];
        const int ldq = (w < 4) ? LK : LV;
        #pragma unroll
        for (int kj = 0; kj < 8; kj++) {
            const float* p = qb + 8 * kj + cq;
            qa[kj][0] = __float_as_uint(p[0]);
            qa[kj][1] = __float_as_uint(p[8 * ldq]);
            qa[kj][2] = __float_as_uint(p[4]);
            qa[kj][3] = __float_as_uint(p[8 * ldq + 4]);
        }
    }
    __syncthreads();   // all fragments extracted before buffers are reused

    auto issueKV = [&](int jt) {
        float* Kd = (jt & 1) ? Kbuf1 : Kbuf0;
        float* Vd = (jt & 1) ? Vbuf1 : Vbuf0;
        int base = jt * 64;
        #pragma unroll
        for (int i = 0; i < 4; i++) {
            int ch = tid + 256 * i;
            int kv = ch >> 4, dq = (ch & 15) * 4;
            cpa16(smem_u32(&Kd[kv * LK + dq]),
                  Kg + (size_t)(base + kv) * DMODEL + dq);
            cpa16(smem_u32(&Vd[kv * LV + dq]),
                  Vg + (size_t)(base + kv) * DMODEL + dq);
        }
    };
    issueKV(0);
    cp_commit();

    float o[8][4];
    #pragma unroll
    for (int ni = 0; ni < 8; ni++)
        #pragma unroll
        for (int j = 0; j < 4; j++) o[ni][j] = 0.f;
    float mr0 = -INFINITY, mr1 = -INFINITY, l0 = 0.f, l1 = 0.f;

    const int nt = 2 * qi + 2;
    for (int jt = 0; jt < nt; jt++) {
        if (jt + 1 < nt) issueKV(jt + 1);
        cp_commit();
        cp_wait<1>();
        __syncthreads();

        const float* Kc = (jt & 1) ? Kbuf1 : Kbuf0;
        const float* Vc = (jt & 1) ? Vbuf1 : Vbuf0;

        // S = Q K^T  (16 x 64 per warp)
        float s[8][4];
        #pragma unroll
        for (int ni = 0; ni < 8; ni++)
            #pragma unroll
            for (int j = 0; j < 4; j++) s[ni][j] = 0.f;

        #pragma unroll
        for (int kj = 0; kj < 8; kj++) {
            #pragma unroll
            for (int ni = 0; ni < 8; ni++) {
                uint32_t bf[2];
                const float* p = &Kc[(8 * ni + r) * LK + 8 * kj + cq];
                bf[0] = __float_as_uint(p[0]);
                bf[1] = __float_as_uint(p[4]);
                mma_tf32(s[ni], qa[kj], bf);
            }
        }

        // online softmax
        const int kvb = jt * 64;
        const float scale = 0.125f;   // 1/sqrt(64)
        float rmax0 = -INFINITY, rmax1 = -INFINITY;
        if (kvb + 63 > qbase + 16 * w) {   // diagonal tiles: mask
            const int row0 = qbase + 16 * w + r;
            const int row1 = row0 + 8;
            #pragma unroll
            for (int ni = 0; ni < 8; ni++) {
                int c0 = kvb + 8 * ni + 2 * cq;
                float v0 = (c0     > row0) ? -INFINITY : s[ni][0] * scale;
                float v1 = (c0 + 1 > row0) ? -INFINITY : s[ni][1] * scale;
                float v2 = (c0     > row1) ? -INFINITY : s[ni][2] * scale;
                float v3 = (c0 + 1 > row1) ? -INFINITY : s[ni][3] * scale;
                s[ni][0] = v0; s[ni][1] = v1; s[ni][2] = v2; s[ni][3] = v3;
                rmax0 = fmaxf(rmax0, fmaxf(v0, v1));
                rmax1 = fmaxf(rmax1, fmaxf(v2, v3));
            }
        } else {
            #pragma unroll
            for (int ni = 0; ni < 8; ni++) {
                float v0 = s[ni][0] * scale, v1 = s[ni][1] * scale;
                float v2 = s[ni][2] * scale, v3 = s[ni][3] * scale;
                s[ni][0] = v0; s[ni][1] = v1; s[ni][2] = v2; s[ni][3] = v3;
                rmax0 = fmaxf(rmax0, fmaxf(v0, v1));
                rmax1 = fmaxf(rmax1, fmaxf(v2, v3));
            }
        }
        #pragma unroll
        for (int off = 1; off < 4; off <<= 1) {
            rmax0 = fmaxf(rmax0, __shfl_xor_sync(0xffffffffu, rmax0, off));
            rmax1 = fmaxf(rmax1, __shfl_xor_sync(0xffffffffu, rmax1, off));
        }
        const float mn0 = fmaxf(mr0, rmax0);
        const float mn1 = fmaxf(mr1, rmax1);
        const float al0 = __expf(mr0 - mn0);
        const float al1 = __expf(mr1 - mn1);
        mr0 = mn0; mr1 = mn1;

        float rs0 = 0.f, rs1 = 0.f;
        #pragma unroll
        for (int ni = 0; ni < 8; ni++) {
            s[ni][0] = __expf(s[ni][0] - mn0);
            s[ni][1] = __expf(s[ni][1] - mn0);
            s[ni][2] = __expf(s[ni][2] - mn1);
            s[ni][3] = __expf(s[ni][3] - mn1);
            rs0 += s[ni][0] + s[ni][1];
            rs1 += s[ni][2] + s[ni][3];
        }
        #pragma unroll
        for (int off = 1; off < 4; off <<= 1) {
            rs0 += __shfl_xor_sync(0xffffffffu, rs0, off);
            rs1 += __shfl_xor_sync(0xffffffffu, rs1, off);
        }
        l0 = l0 * al0 + rs0;
        l1 = l1 * al1 + rs1;
        #pragma unroll
        for (int ni = 0; ni < 8; ni++) {
            o[ni][0] *= al0; o[ni][1] *= al0;
            o[ni][2] *= al1; o[ni][3] *= al1;
        }

        // repack P: C-fragment (s) -> A-fragment (pa) via shuffles, tf32-rounded.
        // target a0 = P(r, 8k+cq) lives at lane 4r+(cq>>1), element cq&1;
        //        a2 = P(r, 8k+cq+4) at lane 4r+2+(cq>>1), element cq&1;
        //        a1/a3 same lanes, elements 2+(cq&1).
        uint32_t pa[8][4];
        const int srcA = 4 * r + (cq >> 1);
        const int srcB = srcA + 2;
        const bool oddc = (cq & 1);
        #pragma unroll
        for (int ni = 0; ni < 8; ni++) {
            float p0 = to_tf32(s[ni][0]);
            float p1 = to_tf32(s[ni][1]);
            float p2 = to_tf32(s[ni][2]);
            float p3 = to_tf32(s[ni][3]);
            float a0a = __shfl_sync(0xffffffffu, p0, srcA);
            float a0b = __shfl_sync(0xffffffffu, p1, srcA);
            float a1a = __shfl_sync(0xffffffffu, p2, srcA);
            float a1b = __shfl_sync(0xffffffffu, p3, srcA);
            float a2a = __shfl_sync(0xffffffffu, p0, srcB);
            float a2b = __shfl_sync(0xffffffffu, p1, srcB);
            float a3a = __shfl_sync(0xffffffffu, p2, srcB);
            float a3b = __shfl_sync(0xffffffffu, p3, srcB);
            pa[ni][0] = __float_as_uint(oddc ? a0b : a0a);
            pa[ni][1] = __float_as_uint(oddc ? a1b : a1a);
            pa[ni][2] = __float_as_uint(oddc ? a2b : a2a);
            pa[ni][3] = __float_as_uint(oddc ? a3b : a3a);
        }

        // O += P V
        #pragma unroll
        for (int kj = 0; kj < 8; kj++) {
            #pragma unroll
            for (int ni = 0; ni < 8; ni++) {
                uint32_t bf[2];
                const float* vp = &Vc[(8 * kj + cq) * LV + 8 * ni + r];
                bf[0] = __float_as_uint(vp[0]);
                bf[1] = __float_as_uint(vp[4 * LV]);
                mma_tf32(o[ni], pa[kj], bf);
            }
        }
        __syncthreads();   // protect K/V buffer reuse by next-next issue
    }

    // epilogue: normalize and store (final GEMM does its own tf32 rounding)
    const float inv0 = 1.f / l0, inv1 = 1.f / l1;
    const int row0 = qbase + 16 * w + r;
    #pragma unroll
    for (int ni = 0; ni < 8; ni++) {
        int col = 8 * ni + 2 * cq;
        float2 v0 = make_float2(o[ni][0] * inv0, o[ni][1] * inv0);
        float2 v1 = make_float2(o[ni][2] * inv1, o[ni][3] * inv1);
        *(float2*)&O[headoff + (size_t)row0 * DMODEL + col] = v0;
        *(float2*)&O[headoff + (size_t)(row0 + 8) * DMODEL + col] = v1;
    }
}

// ---------------------------------------------------------------------------
extern "C" void kernel_launch(void* const* d_in, const int* in_sizes, int n_in,
                              void* d_out, int out_size)
{
    const float* q  = (const float*)d_in[0];
    const float* k  = (const float*)d_in[1];
    const float* v  = (const float*)d_in[2];
    const float* Wq = (const float*)d_in[3];
    const float* bq = (const float*)d_in[4];
    const float* Wk = (const float*)d_in[5];
    const float* bk = (const float*)d_in[6];
    const float* Wv = (const float*)d_in[7];
    const float* bv = (const float*)d_in[8];
    const float* Wo = (const float*)d_in[9];
    const float* bo = (const float*)d_in[10];
    float* out = (float*)d_out;

    float *gQ, *gK, *gV, *gA;
    cudaGetSymbolAddress((void**)&gQ, g_Q);
    cudaGetSymbolAddress((void**)&gK, g_K);
    cudaGetSymbolAddress((void**)&gV, g_V);
    cudaGetSymbolAddress((void**)&gA, g_A);

    const int gemm_smem = 3 * G_STG * (int)sizeof(float);   // 107520
    cudaFuncSetAttribute(gemm_tf32_kernel,
                         cudaFuncAttributeMaxDynamicSharedMemorySize, gemm_smem);

    // batched Q/K/V projections (rounded outputs feed attention)
    const dim3 gqkv(DMODEL / 128, MTOK / 128, 3);   // (8, 64, 3)
    gemm_tf32_kernel<<<gqkv, 256, gemm_smem>>>(
        q, k, v,  Wq, Wk, Wv,  bq, bk, bv,  gQ, gK, gV, 1);

    const int attn_smem = 2 * (ATT_K + ATT_V) * (int)sizeof(float);   // 71680
    cudaFuncSetAttribute(attn_tf32_kernel,
                         cudaFuncAttributeMaxDynamicSharedMemorySize, attn_smem);
    const dim3 agrid(SEQ / 128, BATCH * HEADS);  // (16, 64)
    attn_tf32_kernel<<<agrid, 256, attn_smem>>>(gQ, gK, gV, gA);

    // output projection (raw fp32 out)
    const dim3 gout(DMODEL / 128, MTOK / 128, 1);
    gemm_tf32_kernel<<<gout, 256, gemm_smem>>>(
        gA, gA, gA,  Wo, Wo, Wo,  bo, bo, bo,  out, out, out, 0);
}